// round 14
// baseline (speedup 1.0000x reference)
#include <cuda_runtime.h>
#include <math.h>
#include <stdint.h>

#define Bn 64
#define Tn 512
#define Hn 768
#define Ln 25

__device__ __align__(16) float g_eem  [Bn * Tn * Ln];
__device__ __align__(16) float g_emtag[Bn * Tn];
__device__ float g_llh[Bn];
__device__ int   g_cnt;

typedef unsigned long long ull;

__device__ __forceinline__ ull fma2(ull a, ull b, ull c) {
    ull d; asm("fma.rn.f32x2 %0, %1, %2, %3;" : "=l"(d) : "l"(a), "l"(b), "l"(c)); return d;
}
__device__ __forceinline__ ull mul2(ull a, ull b) {
    ull d; asm("mul.rn.f32x2 %0, %1, %2;" : "=l"(d) : "l"(a), "l"(b)); return d;
}
__device__ __forceinline__ ull add2(ull a, ull b) {
    ull d; asm("add.rn.f32x2 %0, %1, %2;" : "=l"(d) : "l"(a), "l"(b)); return d;
}
__device__ __forceinline__ float lo2(ull a) {
    unsigned l, h; asm("mov.b64 {%0, %1}, %2;" : "=r"(l), "=r"(h) : "l"(a)); return __uint_as_float(l);
}
__device__ __forceinline__ float hi2(ull a) {
    unsigned l, h; asm("mov.b64 {%0, %1}, %2;" : "=r"(l), "=r"(h) : "l"(a)); return __uint_as_float(h);
}
__device__ __forceinline__ ull pack2(float l, float h) {
    ull d; asm("mov.b64 %0, {%1, %2};" : "=l"(d) : "r"(__float_as_uint(l)), "r"(__float_as_uint(h))); return d;
}
__device__ __forceinline__ uint32_t smem_u32(const void* p) {
    uint32_t a; asm("{ .reg .u64 t; cvta.to.shared.u64 t, %1; cvt.u32.u64 %0, t; }" : "=r"(a) : "l"(p));
    return a;
}
__device__ __forceinline__ void cp16(uint32_t dst, const void* src) {
    asm volatile("cp.async.cg.shared.global [%0], [%1], 16;" :: "r"(dst), "l"(src) : "memory");
}
__device__ __forceinline__ void cp4(uint32_t dst, const void* src) {
    asm volatile("cp.async.ca.shared.global [%0], [%1], 4;" :: "r"(dst), "l"(src) : "memory");
}
#define CP_COMMIT() asm volatile("cp.async.commit_group;" ::: "memory")

#define MMA(D, A0, A1, A2, A3, B0, B1)                                          \
    asm volatile(                                                               \
        "mma.sync.aligned.m16n8k8.row.col.f32.tf32.tf32.f32 "                   \
        "{%0,%1,%2,%3}, {%4,%5,%6,%7}, {%8,%9}, {%0,%1,%2,%3};"                 \
        : "+f"((D)[0]), "+f"((D)[1]), "+f"((D)[2]), "+f"((D)[3])                \
        : "r"(A0), "r"(A1), "r"(A2), "r"(A3), "r"(B0), "r"(B1));

// ---------------------------------------------------------------------------
// Kernel 1: GEMM via mma.sync tf32 — 512 blocks x 64 rows (round-13, proven).
// ---------------------------------------------------------------------------
#define SA0   0
#define SA1   9216
#define SW0   18432
#define SW1   23552
#define SBIAS 28672
#define GSMEM 28800

__global__ __launch_bounds__(128) void gemm_kernel(const float* __restrict__ X,
                                                   const float* __restrict__ W,
                                                   const float* __restrict__ bias,
                                                   const int*   __restrict__ labels) {
    extern __shared__ char smem[];
    const uint32_t sb = smem_u32(smem);
    const int tid  = threadIdx.x;
    const int wid  = tid >> 5;
    const int lid  = tid & 31;
    const int grp  = lid >> 2;
    const int qd   = lid & 3;
    const int row0 = blockIdx.x * 64;

    if (blockIdx.x == 0 && tid == 0) g_cnt = 0;

    float* bias_s = (float*)(smem + SBIAS);
    if (tid < 32) bias_s[tid] = (tid < Ln) ? bias[tid] : 0.f;

    float c_[4][4];
#pragma unroll
    for (int nt = 0; nt < 4; ++nt)
#pragma unroll
        for (int r = 0; r < 4; ++r) c_[nt][r] = 0.f;

#define STAGE(CK, BUF)                                                          \
    {                                                                           \
        uint32_t ab = sb + ((BUF) ? SA1 : SA0);                                 \
        uint32_t wb = sb + ((BUF) ? SW1 : SW0);                                 \
        _Pragma("unroll")                                                       \
        for (int t = 0; t < 4; ++t) {                                           \
            int i = t * 128 + tid;                                              \
            int r = i >> 3, q = i & 7;                                          \
            cp16(ab + (r * 36 + q * 4) * 4,                                     \
                 X + (size_t)(row0 + r) * Hn + (CK) * 32 + q * 4);              \
        }                                                                       \
        _Pragma("unroll")                                                       \
        for (int t = 0; t < 7; ++t) {                                           \
            int i = t * 128 + tid;                                              \
            if (i < 800) {                                                      \
                int k = i / 25, n = i - k * 25;                                 \
                cp4(wb + (k * 40 + n) * 4, W + (CK) * 800 + i);                 \
            }                                                                   \
        }                                                                       \
        CP_COMMIT();                                                            \
    }

    STAGE(0, 0)
    STAGE(1, 1)

    for (int ck = 0; ck < 24; ++ck) {
        if (ck < 23) asm volatile("cp.async.wait_group 1;" ::: "memory");
        else         asm volatile("cp.async.wait_group 0;" ::: "memory");
        __syncthreads();

        const int buf = ck & 1;
        const float* As = (const float*)(smem + (buf ? SA1 : SA0));
        const float* Ws = (const float*)(smem + (buf ? SW1 : SW0));

#pragma unroll
        for (int ks = 0; ks < 4; ++ks) {
            const int k0 = ks * 8;
            uint32_t a0, a1, a2, a3, b[4][2];
            int r = wid * 16 + grp;
            a0 = __float_as_uint(As[r * 36 + k0 + qd]);
            a1 = __float_as_uint(As[(r + 8) * 36 + k0 + qd]);
            a2 = __float_as_uint(As[r * 36 + k0 + qd + 4]);
            a3 = __float_as_uint(As[(r + 8) * 36 + k0 + qd + 4]);
#pragma unroll
            for (int nt = 0; nt < 4; ++nt) {
                int n = nt * 8 + grp;
                float b0 = (n < Ln) ? Ws[(k0 + qd) * 40 + n] : 0.f;
                float b1 = (n < Ln) ? Ws[(k0 + qd + 4) * 40 + n] : 0.f;
                b[nt][0] = __float_as_uint(b0);
                b[nt][1] = __float_as_uint(b1);
            }
#pragma unroll
            for (int nt = 0; nt < 4; ++nt)
                MMA(c_[nt], a0, a1, a2, a3, b[nt][0], b[nt][1])
        }
        __syncthreads();
        if (ck + 2 < 24) STAGE(ck + 2, buf)
    }

    float* pem = (float*)(smem + 0);
    float* pee = (float*)(smem + 6400);
    {
        int rb = wid * 16 + grp;
#pragma unroll
        for (int nt = 0; nt < 4; ++nt) {
            int col = nt * 8 + 2 * qd;
            if (col < Ln) {
                float v0 = c_[nt][0] + bias_s[col];
                float v2 = c_[nt][2] + bias_s[col];
                pem[rb * Ln + col]       = v0;
                pem[(rb + 8) * Ln + col] = v2;
                pee[rb * Ln + col]       = __expf(v0);
                pee[(rb + 8) * Ln + col] = __expf(v2);
            }
            if (col + 1 < Ln) {
                float v1 = c_[nt][1] + bias_s[col + 1];
                float v3 = c_[nt][3] + bias_s[col + 1];
                pem[rb * Ln + col + 1]       = v1;
                pem[(rb + 8) * Ln + col + 1] = v3;
                pee[rb * Ln + col + 1]       = __expf(v1);
                pee[(rb + 8) * Ln + col + 1] = __expf(v3);
            }
        }
    }
    __syncthreads();
    {
        if (tid < 64) {
            int lab = labels[row0 + tid];
            g_emtag[row0 + tid] = pem[tid * Ln + lab];
        }
        const float4* s1 = (const float4*)pee;
        float4* g1 = (float4*)(g_eem + (size_t)row0 * Ln);
#pragma unroll
        for (int t = 0; t < 4; ++t) {
            int i = t * 128 + tid;
            if (i < 400) g1[i] = s1[i];
        }
    }
}

// ---------------------------------------------------------------------------
// Kernel 2: 3-segment CRF. One block/batch, 28 warps:
//   warp 0 : fwd  p = a0^T G1..G170
//   warp 1 : bwd  w = G342..G511 e
//   warps 2-26 : columns m_j = G171..G341 e_j
//   warp 27: numerator
// Combine in-block: Z = sum_j (p.m_j) w_j exp(Cj).
// ---------------------------------------------------------------------------
#define LN2F 0.6931471805599453f

#define CEMS  0           // 51200 B  exp(em)[512][25]
#define CPBF  51200       // 28*128 = 3584 B
#define CMSK  54784       // 2048 B
#define CCP   56832       // 128 B  cmb_p
#define CCW   56960       // 128 B  cmb_w
#define CDV   57088       // 128 B  dvals
#define CDC   57216       // 128 B  dC
#define CSC   57344       // 64 B   scalars
#define CSMEM 57408

#define LDW13(PB)                                                               \
        ull w0,w1,w2,w3,w4,w5,w6,w7,w8,w9,w10,w11,w12;                          \
        asm volatile("ld.shared.v2.u64 {%0,%1}, [%2];"                          \
                     : "=l"(w0), "=l"(w1) : "r"(PB));                           \
        asm volatile("ld.shared.v2.u64 {%0,%1}, [%2];"                          \
                     : "=l"(w2), "=l"(w3) : "r"((PB) + 16));                    \
        asm volatile("ld.shared.v2.u64 {%0,%1}, [%2];"                          \
                     : "=l"(w4), "=l"(w5) : "r"((PB) + 32));                    \
        asm volatile("ld.shared.v2.u64 {%0,%1}, [%2];"                          \
                     : "=l"(w6), "=l"(w7) : "r"((PB) + 48));                    \
        asm volatile("ld.shared.v2.u64 {%0,%1}, [%2];"                          \
                     : "=l"(w8), "=l"(w9) : "r"((PB) + 64));                    \
        asm volatile("ld.shared.v2.u64 {%0,%1}, [%2];"                          \
                     : "=l"(w10), "=l"(w11) : "r"((PB) + 80));                  \
        asm volatile("ld.shared.u64 %0, [%1];"                                  \
                     : "=l"(w12) : "r"((PB) + 96));

#define DOT13(ET)                                                               \
        ull A0 = mul2(w0, (ET)[0]);                                             \
        ull A1 = mul2(w1, (ET)[1]);                                             \
        ull A2 = mul2(w2, (ET)[2]);                                             \
        ull A3 = mul2(w3, (ET)[3]);                                             \
        ull A4 = mul2(w4, (ET)[4]);                                             \
        ull A5 = mul2(w5, (ET)[5]);                                             \
        ull A6 = mul2(w6, (ET)[6]);                                             \
        A0 = fma2(w7,  (ET)[7],  A0);                                           \
        A1 = fma2(w8,  (ET)[8],  A1);                                           \
        A2 = fma2(w9,  (ET)[9],  A2);                                           \
        A3 = fma2(w10, (ET)[10], A3);                                           \
        A4 = fma2(w11, (ET)[11], A4);                                           \
        A5 = fma2(w12, (ET)[12], A5);                                           \
        ull T0 = add2(A0, A1);                                                  \
        ull T1 = add2(A2, A3);                                                  \
        ull T2 = add2(A4, A5);                                                  \
        T0 = add2(T0, T1);                                                      \
        T2 = add2(T2, A6);                                                      \
        T0 = add2(T0, T2);

// forward step at absolute time T (prefetch T+1)
#define FSTEP(T)                                                                \
    {                                                                           \
        float emn = emsb[((T) + 1) * Ln + jc];                                  \
        int   mn  = smaskp[(T) + 1];                                            \
        asm volatile("st.shared.b32 [%0], %1;"                                  \
                     :: "r"(pbase + 4u * (unsigned)j),                          \
                        "r"(__float_as_uint(p)) : "memory");                    \
        LDW13(pbase)                                                            \
        DOT13(et2)                                                              \
        float pn = (lo2(T0) + hi2(T0)) * emc;                                   \
        p = mcur ? pn : p;                                                      \
        emc = emn; mcur = mn;                                                   \
    }

// backward step at absolute time T (prefetch T-1)
#define BSTEP(T)                                                                \
    {                                                                           \
        float emn = emsb[((T) - 1) * Ln + jc] * lane_okf;                       \
        int   mn  = smaskp[(T) - 1];                                            \
        float w   = p * emc;                                                    \
        asm volatile("st.shared.b32 [%0], %1;"                                  \
                     :: "r"(pbase + 4u * (unsigned)j),                          \
                        "r"(__float_as_uint(w)) : "memory");                    \
        LDW13(pbase)                                                            \
        DOT13(et2)                                                              \
        float pn = lo2(T0) + hi2(T0);                                           \
        p = mcur ? pn : p;                                                      \
        emc = emn; mcur = mn;                                                   \
    }

#define CRF_RENORM                                                              \
    {                                                                           \
        unsigned mx = __reduce_max_sync(0xffffffffu, __float_as_uint(p));       \
        int e = (int)(mx >> 23);                                                \
        float sc = __uint_as_float((unsigned)(253 - e) << 23);                  \
        p *= sc;                                                                \
        C += (float)(e - 126) * LN2F;                                           \
    }

__global__ __launch_bounds__(896) void crf_kernel(const int* __restrict__ mask,
                                                  const int* __restrict__ labels,
                                                  const float* __restrict__ trans,
                                                  const float* __restrict__ start_t,
                                                  const float* __restrict__ end_t,
                                                  float* __restrict__ out) {
    extern __shared__ char cs[];
    float* emsb   = (float*)(cs + CEMS);
    int*   smaskp = (int*)  (cs + CMSK);
    float* cmbp   = (float*)(cs + CCP);
    float* cmbw   = (float*)(cs + CCW);
    float* dvals  = (float*)(cs + CDV);
    float* dC     = (float*)(cs + CDC);
    float* scal   = (float*)(cs + CSC);   // [0]=C_p [1]=C_w [2]=num

    const int b    = blockIdx.x;
    const int tid  = threadIdx.x;
    const int wid  = tid >> 5;
    const int j    = tid & 31;
    const int jc   = (j < Ln) ? j : (Ln - 1);
    const bool lane_ok   = (j < Ln);
    const float lane_okf = lane_ok ? 1.f : 0.f;
    const uint32_t pbase = smem_u32(cs + CPBF) + (unsigned)wid * 128u;

    const float* eemB   = g_eem + (size_t)b * Tn * Ln;
    const float* emtagb = g_emtag + b * Tn;
    const int*   lb     = labels + b * Tn;

    // ---- stage exp(em) (51.2KB) + mask ----
    {
        const float4* src = (const float4*)eemB;
        uint32_t dstb = smem_u32(emsb);
        for (int i = tid; i < 3200; i += 896)
            cp16(dstb + 16u * (unsigned)i, src + i);
        CP_COMMIT();
    }
    for (int t = tid; t < Tn; t += 896) smaskp[t] = mask[b * Tn + t];
    asm volatile("cp.async.wait_group 0;" ::: "memory");
    __syncthreads();

    float p = 0.f, C = 0.f;

    if (wid == 0) {
        // ===== forward: p = a0^T G1..G170 =====
        ull et2[13];
#pragma unroll
        for (int i = 0; i < 13; ++i) {
            float lo = __expf(trans[(2 * i) * Ln + jc]);
            float hi = (2 * i + 1 < Ln) ? __expf(trans[(2 * i + 1) * Ln + jc]) : 0.f;
            et2[i] = pack2(lo, hi);
        }
        p = __expf(start_t[jc]) * emsb[jc];
        float emc = emsb[Ln + jc];
        int   mcur = smaskp[1];
        int t = 1;
        for (int g = 0; g < 10; ++g) {
#pragma unroll
            for (int u = 0; u < 16; ++u) { FSTEP(t) ++t; }
            CRF_RENORM
        }
#pragma unroll
        for (int u = 0; u < 10; ++u) { FSTEP(t) ++t; }
        CRF_RENORM
        cmbp[j] = lane_ok ? p : 0.f;
        if (j == 0) scal[0] = C;
    } else if (wid == 1) {
        // ===== backward: w = G342..G511 e =====
        ull et2[13];
#pragma unroll
        for (int i = 0; i < 13; ++i) {
            float lo = __expf(trans[jc * Ln + 2 * i]);
            float hi = (2 * i + 1 < Ln) ? __expf(trans[jc * Ln + 2 * i + 1]) : 0.f;
            et2[i] = pack2(lo, hi);
        }
        p = lane_ok ? __expf(end_t[jc]) : 0.f;
        float emc = emsb[511 * Ln + jc] * lane_okf;
        int   mcur = smaskp[511];
        int t = 511;
        for (int g = 0; g < 10; ++g) {
#pragma unroll
            for (int u = 0; u < 16; ++u) { BSTEP(t) --t; }
            CRF_RENORM
        }
#pragma unroll
        for (int u = 0; u < 10; ++u) { BSTEP(t) --t; }
        CRF_RENORM
        cmbw[j] = lane_ok ? p : 0.f;
        if (j == 0) scal[1] = C;
    } else if (wid < 27) {
        // ===== column m_colj = G171..G341 e_colj =====
        const int colj = wid - 2;
        ull et2[13];
#pragma unroll
        for (int i = 0; i < 13; ++i) {
            float lo = __expf(trans[jc * Ln + 2 * i]);
            float hi = (2 * i + 1 < Ln) ? __expf(trans[jc * Ln + 2 * i + 1]) : 0.f;
            et2[i] = pack2(lo, hi);
        }
        p = (j == colj) ? 1.f : 0.f;
        float emc = emsb[341 * Ln + jc] * lane_okf;
        int   mcur = smaskp[341];
        int t = 341;
        for (int g = 0; g < 10; ++g) {
#pragma unroll
            for (int u = 0; u < 16; ++u) { BSTEP(t) --t; }
            CRF_RENORM
        }
#pragma unroll
        for (int u = 0; u < 11; ++u) { BSTEP(t) --t; }
        CRF_RENORM
    } else {
        // ===== numerator =====
        float numv = 0.f; int msum = 0;
        for (int t = j; t < Tn; t += 32) {
            int m = smaskp[t];
            msum += m;
            if (t == 0)  numv += start_t[lb[0]] + emtagb[0];
            else if (m)  numv += trans[lb[t - 1] * Ln + lb[t]] + emtagb[t];
        }
#pragma unroll
        for (int off = 16; off; off >>= 1) {
            numv += __shfl_xor_sync(0xffffffffu, numv, off);
            msum += __shfl_xor_sync(0xffffffffu, msum, off);
        }
        if (j == 0) scal[2] = numv + end_t[lb[msum - 1]];
    }
    __syncthreads();

    // column warps: d_j = p . m_j
    if (wid >= 2 && wid < 27) {
        float val = lane_ok ? cmbp[j] * p : 0.f;
#pragma unroll
        for (int off = 16; off; off >>= 1)
            val += __shfl_xor_sync(0xffffffffu, val, off);
        if (j == 0) { dvals[wid - 2] = val; dC[wid - 2] = C; }
    }
    __syncthreads();

    if (wid == 0) {
        float d  = lane_ok ? dvals[j] : 0.f;
        float Cj = lane_ok ? dC[j]    : -1e30f;
        float Cmax = Cj;
#pragma unroll
        for (int off = 16; off; off >>= 1)
            Cmax = fmaxf(Cmax, __shfl_xor_sync(0xffffffffu, Cmax, off));
        float term = lane_ok ? d * cmbw[j] * __expf(Cj - Cmax) : 0.f;
#pragma unroll
        for (int off = 16; off; off >>= 1)
            term += __shfl_xor_sync(0xffffffffu, term, off);
        if (j == 0) {
            float denom = scal[0] + scal[1] + Cmax + __logf(term);
            g_llh[b] = scal[2] - denom;
            __threadfence();
            int old = atomicAdd(&g_cnt, 1);
            if (old == Bn - 1) {
                __threadfence();
                float s = 0.f;
#pragma unroll 8
                for (int i = 0; i < Bn; ++i) s += __ldcv(&g_llh[i]);
                out[0] = -s * (1.0f / 64.0f);
            }
        }
    }
}

// ---------------------------------------------------------------------------
extern "C" void kernel_launch(void* const* d_in, const int* in_sizes, int n_in,
                              void* d_out, int out_size) {
    const float* X      = (const float*)d_in[0];
    const int*   mask   = (const int*)  d_in[1];
    const int*   labels = (const int*)  d_in[2];
    const float* W      = (const float*)d_in[3];
    const float* bias   = (const float*)d_in[4];
    const float* trans  = (const float*)d_in[5];
    const float* st     = (const float*)d_in[6];
    const float* en     = (const float*)d_in[7];
    float* out = (float*)d_out;

    cudaFuncSetAttribute(crf_kernel,
                         cudaFuncAttributeMaxDynamicSharedMemorySize, CSMEM);

    gemm_kernel<<<512, 128, GSMEM>>>(X, W, bias, labels);
    crf_kernel<<<Bn, 896, CSMEM>>>(mask, labels, trans, st, en, out);
}

// round 15
// speedup vs baseline: 1.1434x; 1.1434x over previous
#include <cuda_runtime.h>
#include <math.h>
#include <stdint.h>

#define Bn 64
#define Tn 512
#define Hn 768
#define Ln 25

__device__ __align__(16) float g_eem  [Bn * Tn * Ln];
__device__ __align__(16) float g_emtag[Bn * Tn];
__device__ __align__(16) float g_P [Bn][32];      // fwd result
__device__ __align__(16) float g_Wv[Bn][32];      // bwd result
__device__ __align__(16) float g_M [Bn][25][28];  // middle columns
__device__ float g_MC [Bn][32];                   // column C's
__device__ float g_Cpw[Bn][2];                    // fwd/bwd C
__device__ float g_num[Bn];
__device__ float g_llh[Bn];
__device__ int   g_done[Bn];
__device__ int   g_cnt;

typedef unsigned long long ull;

__device__ __forceinline__ ull fma2(ull a, ull b, ull c) {
    ull d; asm("fma.rn.f32x2 %0, %1, %2, %3;" : "=l"(d) : "l"(a), "l"(b), "l"(c)); return d;
}
__device__ __forceinline__ ull mul2(ull a, ull b) {
    ull d; asm("mul.rn.f32x2 %0, %1, %2;" : "=l"(d) : "l"(a), "l"(b)); return d;
}
__device__ __forceinline__ ull add2(ull a, ull b) {
    ull d; asm("add.rn.f32x2 %0, %1, %2;" : "=l"(d) : "l"(a), "l"(b)); return d;
}
__device__ __forceinline__ float lo2(ull a) {
    unsigned l, h; asm("mov.b64 {%0, %1}, %2;" : "=r"(l), "=r"(h) : "l"(a)); return __uint_as_float(l);
}
__device__ __forceinline__ float hi2(ull a) {
    unsigned l, h; asm("mov.b64 {%0, %1}, %2;" : "=r"(l), "=r"(h) : "l"(a)); return __uint_as_float(h);
}
__device__ __forceinline__ ull pack2(float l, float h) {
    ull d; asm("mov.b64 %0, {%1, %2};" : "=l"(d) : "r"(__float_as_uint(l)), "r"(__float_as_uint(h))); return d;
}
__device__ __forceinline__ uint32_t smem_u32(const void* p) {
    uint32_t a; asm("{ .reg .u64 t; cvta.to.shared.u64 t, %1; cvt.u32.u64 %0, t; }" : "=r"(a) : "l"(p));
    return a;
}
__device__ __forceinline__ void cp16(uint32_t dst, const void* src) {
    asm volatile("cp.async.cg.shared.global [%0], [%1], 16;" :: "r"(dst), "l"(src) : "memory");
}
__device__ __forceinline__ void cp4(uint32_t dst, const void* src) {
    asm volatile("cp.async.ca.shared.global [%0], [%1], 4;" :: "r"(dst), "l"(src) : "memory");
}
#define CP_COMMIT() asm volatile("cp.async.commit_group;" ::: "memory")

#define MMA(D, A0, A1, A2, A3, B0, B1)                                          \
    asm volatile(                                                               \
        "mma.sync.aligned.m16n8k8.row.col.f32.tf32.tf32.f32 "                   \
        "{%0,%1,%2,%3}, {%4,%5,%6,%7}, {%8,%9}, {%0,%1,%2,%3};"                 \
        : "+f"((D)[0]), "+f"((D)[1]), "+f"((D)[2]), "+f"((D)[3])                \
        : "r"(A0), "r"(A1), "r"(A2), "r"(A3), "r"(B0), "r"(B1));

// ---------------------------------------------------------------------------
// Kernel 1: GEMM via mma.sync tf32 — 512 blocks x 64 rows (round-13, proven).
// ---------------------------------------------------------------------------
#define SA0   0
#define SA1   9216
#define SW0   18432
#define SW1   23552
#define SBIAS 28672
#define GSMEM 28800

__global__ __launch_bounds__(128) void gemm_kernel(const float* __restrict__ X,
                                                   const float* __restrict__ W,
                                                   const float* __restrict__ bias,
                                                   const int*   __restrict__ labels) {
    extern __shared__ char smem[];
    const uint32_t sb = smem_u32(smem);
    const int tid  = threadIdx.x;
    const int wid  = tid >> 5;
    const int lid  = tid & 31;
    const int grp  = lid >> 2;
    const int qd   = lid & 3;
    const int row0 = blockIdx.x * 64;

    if (tid == 0 && blockIdx.x < Bn) g_done[blockIdx.x] = 0;
    if (tid == 0 && blockIdx.x == Bn) g_cnt = 0;

    float* bias_s = (float*)(smem + SBIAS);
    if (tid < 32) bias_s[tid] = (tid < Ln) ? bias[tid] : 0.f;

    float c_[4][4];
#pragma unroll
    for (int nt = 0; nt < 4; ++nt)
#pragma unroll
        for (int r = 0; r < 4; ++r) c_[nt][r] = 0.f;

#define STAGE(CK, BUF)                                                          \
    {                                                                           \
        uint32_t ab = sb + ((BUF) ? SA1 : SA0);                                 \
        uint32_t wb = sb + ((BUF) ? SW1 : SW0);                                 \
        _Pragma("unroll")                                                       \
        for (int t = 0; t < 4; ++t) {                                           \
            int i = t * 128 + tid;                                              \
            int r = i >> 3, q = i & 7;                                          \
            cp16(ab + (r * 36 + q * 4) * 4,                                     \
                 X + (size_t)(row0 + r) * Hn + (CK) * 32 + q * 4);              \
        }                                                                       \
        _Pragma("unroll")                                                       \
        for (int t = 0; t < 7; ++t) {                                           \
            int i = t * 128 + tid;                                              \
            if (i < 800) {                                                      \
                int k = i / 25, n = i - k * 25;                                 \
                cp4(wb + (k * 40 + n) * 4, W + (CK) * 800 + i);                 \
            }                                                                   \
        }                                                                       \
        CP_COMMIT();                                                            \
    }

    STAGE(0, 0)
    STAGE(1, 1)

    for (int ck = 0; ck < 24; ++ck) {
        if (ck < 23) asm volatile("cp.async.wait_group 1;" ::: "memory");
        else         asm volatile("cp.async.wait_group 0;" ::: "memory");
        __syncthreads();

        const int buf = ck & 1;
        const float* As = (const float*)(smem + (buf ? SA1 : SA0));
        const float* Ws = (const float*)(smem + (buf ? SW1 : SW0));

#pragma unroll
        for (int ks = 0; ks < 4; ++ks) {
            const int k0 = ks * 8;
            uint32_t a0, a1, a2, a3, b[4][2];
            int r = wid * 16 + grp;
            a0 = __float_as_uint(As[r * 36 + k0 + qd]);
            a1 = __float_as_uint(As[(r + 8) * 36 + k0 + qd]);
            a2 = __float_as_uint(As[r * 36 + k0 + qd + 4]);
            a3 = __float_as_uint(As[(r + 8) * 36 + k0 + qd + 4]);
#pragma unroll
            for (int nt = 0; nt < 4; ++nt) {
                int n = nt * 8 + grp;
                float b0 = (n < Ln) ? Ws[(k0 + qd) * 40 + n] : 0.f;
                float b1 = (n < Ln) ? Ws[(k0 + qd + 4) * 40 + n] : 0.f;
                b[nt][0] = __float_as_uint(b0);
                b[nt][1] = __float_as_uint(b1);
            }
#pragma unroll
            for (int nt = 0; nt < 4; ++nt)
                MMA(c_[nt], a0, a1, a2, a3, b[nt][0], b[nt][1])
        }
        __syncthreads();
        if (ck + 2 < 24) STAGE(ck + 2, buf)
    }

    float* pem = (float*)(smem + 0);
    float* pee = (float*)(smem + 6400);
    {
        int rb = wid * 16 + grp;
#pragma unroll
        for (int nt = 0; nt < 4; ++nt) {
            int col = nt * 8 + 2 * qd;
            if (col < Ln) {
                float v0 = c_[nt][0] + bias_s[col];
                float v2 = c_[nt][2] + bias_s[col];
                pem[rb * Ln + col]       = v0;
                pem[(rb + 8) * Ln + col] = v2;
                pee[rb * Ln + col]       = __expf(v0);
                pee[(rb + 8) * Ln + col] = __expf(v2);
            }
            if (col + 1 < Ln) {
                float v1 = c_[nt][1] + bias_s[col + 1];
                float v3 = c_[nt][3] + bias_s[col + 1];
                pem[rb * Ln + col + 1]       = v1;
                pem[(rb + 8) * Ln + col + 1] = v3;
                pee[rb * Ln + col + 1]       = __expf(v1);
                pee[(rb + 8) * Ln + col + 1] = __expf(v3);
            }
        }
    }
    __syncthreads();
    {
        if (tid < 64) {
            int lab = labels[row0 + tid];
            g_emtag[row0 + tid] = pem[tid * Ln + lab];
        }
        const float4* s1 = (const float4*)pee;
        float4* g1 = (float4*)(g_eem + (size_t)row0 * Ln);
#pragma unroll
        for (int t = 0; t < 4; ++t) {
            int i = t * 128 + tid;
            if (i < 400) g1[i] = s1[i];
        }
    }
}

// ---------------------------------------------------------------------------
// Kernel 2: 3-segment CRF, DISTRIBUTED. Grid 64*6:
//   r==0  : fwd (t=1..170), bwd (t=511..342), numerator  (3 warps)
//   r=1..5: 5 column chains each, m_j = G171..G341 e_j   (5 warps)
// Last of 6 finishers per batch combines; global last writes out.
// ---------------------------------------------------------------------------
#define LN2F 0.6931471805599453f

#define LDW13(PB)                                                               \
        ull w0,w1,w2,w3,w4,w5,w6,w7,w8,w9,w10,w11,w12;                          \
        asm volatile("ld.shared.v2.u64 {%0,%1}, [%2];"                          \
                     : "=l"(w0), "=l"(w1) : "r"(PB));                           \
        asm volatile("ld.shared.v2.u64 {%0,%1}, [%2];"                          \
                     : "=l"(w2), "=l"(w3) : "r"((PB) + 16));                    \
        asm volatile("ld.shared.v2.u64 {%0,%1}, [%2];"                          \
                     : "=l"(w4), "=l"(w5) : "r"((PB) + 32));                    \
        asm volatile("ld.shared.v2.u64 {%0,%1}, [%2];"                          \
                     : "=l"(w6), "=l"(w7) : "r"((PB) + 48));                    \
        asm volatile("ld.shared.v2.u64 {%0,%1}, [%2];"                          \
                     : "=l"(w8), "=l"(w9) : "r"((PB) + 64));                    \
        asm volatile("ld.shared.v2.u64 {%0,%1}, [%2];"                          \
                     : "=l"(w10), "=l"(w11) : "r"((PB) + 80));                  \
        asm volatile("ld.shared.u64 %0, [%1];"                                  \
                     : "=l"(w12) : "r"((PB) + 96));

#define DOT13(ET)                                                               \
        ull A0 = mul2(w0, (ET)[0]);                                             \
        ull A1 = mul2(w1, (ET)[1]);                                             \
        ull A2 = mul2(w2, (ET)[2]);                                             \
        ull A3 = mul2(w3, (ET)[3]);                                             \
        ull A4 = mul2(w4, (ET)[4]);                                             \
        ull A5 = mul2(w5, (ET)[5]);                                             \
        ull A6 = mul2(w6, (ET)[6]);                                             \
        A0 = fma2(w7,  (ET)[7],  A0);                                           \
        A1 = fma2(w8,  (ET)[8],  A1);                                           \
        A2 = fma2(w9,  (ET)[9],  A2);                                           \
        A3 = fma2(w10, (ET)[10], A3);                                           \
        A4 = fma2(w11, (ET)[11], A4);                                           \
        A5 = fma2(w12, (ET)[12], A5);                                           \
        ull T0 = add2(A0, A1);                                                  \
        ull T1 = add2(A2, A3);                                                  \
        ull T2 = add2(A4, A5);                                                  \
        T0 = add2(T0, T1);                                                      \
        T2 = add2(T2, A6);                                                      \
        T0 = add2(T0, T2);

// forward step; TL = local row of current t, TG = absolute t (for mask)
#define FSTEP(EMS, TL, TG)                                                      \
    {                                                                           \
        float emn = (EMS)[((TL) + 1) * Ln + jc];                                \
        int   mn  = smaskS[(TG) + 1];                                           \
        asm volatile("st.shared.b32 [%0], %1;"                                  \
                     :: "r"(pbase + 4u * (unsigned)j),                          \
                        "r"(__float_as_uint(p)) : "memory");                    \
        LDW13(pbase)                                                            \
        DOT13(et2)                                                              \
        float pn = (lo2(T0) + hi2(T0)) * emc;                                   \
        p = mcur ? pn : p;                                                      \
        emc = emn; mcur = mn;                                                   \
    }

// backward step
#define BSTEP(EMS, TL, TG)                                                      \
    {                                                                           \
        float emn = (EMS)[((TL) - 1) * Ln + jc] * lane_okf;                     \
        int   mn  = smaskS[(TG) - 1];                                           \
        float w   = p * emc;                                                    \
        asm volatile("st.shared.b32 [%0], %1;"                                  \
                     :: "r"(pbase + 4u * (unsigned)j),                          \
                        "r"(__float_as_uint(w)) : "memory");                    \
        LDW13(pbase)                                                            \
        DOT13(et2)                                                              \
        float pn = lo2(T0) + hi2(T0);                                           \
        p = mcur ? pn : p;                                                      \
        emc = emn; mcur = mn;                                                   \
    }

#define CRF_RENORM                                                              \
    {                                                                           \
        unsigned mx = __reduce_max_sync(0xffffffffu, __float_as_uint(p));       \
        int e = (int)(mx >> 23);                                                \
        float sc = __uint_as_float((unsigned)(253 - e) << 23);                  \
        p *= sc;                                                                \
        C += (float)(e - 126) * LN2F;                                           \
    }

__global__ __launch_bounds__(160) void crf_kernel(const int* __restrict__ mask,
                                                  const int* __restrict__ labels,
                                                  const float* __restrict__ trans,
                                                  const float* __restrict__ start_t,
                                                  const float* __restrict__ end_t,
                                                  float* __restrict__ out) {
    __shared__ __align__(16) float emsS[8608];   // A: [0..4299]=rows0..171, [4304..]=rows340..511 ; col: rows168..341
    __shared__ __align__(16) float pbufS[5 * 32];
    __shared__ int   smaskS[Tn];
    __shared__ int   sflag;

    const int b   = blockIdx.x / 6;
    const int r   = blockIdx.x % 6;
    const int tid = threadIdx.x;
    const int wid = tid >> 5;
    const int j   = tid & 31;
    const int jc  = (j < Ln) ? j : (Ln - 1);
    const bool lane_ok   = (j < Ln);
    const float lane_okf = lane_ok ? 1.f : 0.f;
    const uint32_t pbase = smem_u32(pbufS) + (unsigned)wid * 128u;

    const float* eemB   = g_eem + (size_t)b * Tn * Ln;
    const float* emtagb = g_emtag + b * Tn;
    const int*   lb     = labels + b * Tn;

    // ---- stage emissions (segment-local) + mask ----
    {
        uint32_t db = smem_u32(emsS);
        if (r == 0) {
            const float4* s0 = (const float4*)eemB;                 // rows 0..171
            const float4* s1 = (const float4*)(eemB + 8500);        // rows 340..511
            for (int i = tid; i < 1075; i += 160) {
                cp16(db + 16u * (unsigned)i, s0 + i);
                cp16(db + 17216u + 16u * (unsigned)i, s1 + i);
            }
        } else {
            const float4* s0 = (const float4*)(eemB + 4200);        // rows 168..341
            for (int i = tid; i < 1088; i += 160)
                cp16(db + 16u * (unsigned)i, s0 + i);
        }
        CP_COMMIT();
    }
    for (int t = tid; t < Tn; t += 160) smaskS[t] = mask[b * Tn + t];
    asm volatile("cp.async.wait_group 0;" ::: "memory");
    __syncthreads();

    if (r == 0) {
        if (wid == 0) {
            // ===== fwd: p = a0^T G1..G170 ===== (local row = t)
            const float* ems = emsS;
            ull et2[13];
#pragma unroll
            for (int i = 0; i < 13; ++i) {
                float lo = __expf(trans[(2 * i) * Ln + jc]);
                float hi = (2 * i + 1 < Ln) ? __expf(trans[(2 * i + 1) * Ln + jc]) : 0.f;
                et2[i] = pack2(lo, hi);
            }
            float p = __expf(start_t[jc]) * ems[jc];
            float C = 0.f;
            float emc = ems[Ln + jc];
            int   mcur = smaskS[1];
            int t = 1;
            for (int g = 0; g < 10; ++g) {
#pragma unroll
                for (int u = 0; u < 16; ++u) { FSTEP(ems, t, t) ++t; }
                CRF_RENORM
            }
#pragma unroll
            for (int u = 0; u < 10; ++u) { FSTEP(ems, t, t) ++t; }
            CRF_RENORM
            g_P[b][j] = lane_ok ? p : 0.f;
            if (j == 0) g_Cpw[b][0] = C;
        } else if (wid == 1) {
            // ===== bwd: w = G342..G511 e ===== (local row = t-340)
            const float* ems = emsS + 4304;
            ull et2[13];
#pragma unroll
            for (int i = 0; i < 13; ++i) {
                float lo = __expf(trans[jc * Ln + 2 * i]);
                float hi = (2 * i + 1 < Ln) ? __expf(trans[jc * Ln + 2 * i + 1]) : 0.f;
                et2[i] = pack2(lo, hi);
            }
            float p = lane_ok ? __expf(end_t[jc]) : 0.f;
            float C = 0.f;
            float emc = ems[171 * Ln + jc] * lane_okf;   // row 511
            int   mcur = smaskS[511];
            int t = 511;
            for (int g = 0; g < 10; ++g) {
#pragma unroll
                for (int u = 0; u < 16; ++u) { BSTEP(ems, t - 340, t) --t; }
                CRF_RENORM
            }
#pragma unroll
            for (int u = 0; u < 10; ++u) { BSTEP(ems, t - 340, t) --t; }
            CRF_RENORM
            g_Wv[b][j] = lane_ok ? p : 0.f;
            if (j == 0) g_Cpw[b][1] = C;
        } else if (wid == 2) {
            // ===== numerator =====
            float numv = 0.f; int msum = 0;
            for (int t = j; t < Tn; t += 32) {
                int m = smaskS[t];
                msum += m;
                if (t == 0)  numv += start_t[lb[0]] + emtagb[0];
                else if (m)  numv += trans[lb[t - 1] * Ln + lb[t]] + emtagb[t];
            }
#pragma unroll
            for (int off = 16; off; off >>= 1) {
                numv += __shfl_xor_sync(0xffffffffu, numv, off);
                msum += __shfl_xor_sync(0xffffffffu, msum, off);
            }
            if (j == 0) g_num[b] = numv + end_t[lb[msum - 1]];
        }
    } else {
        // ===== column m_colj = G171..G341 e_colj ===== (local row = t-168)
        const int colj = (r - 1) * 5 + wid;   // 0..24
        const float* ems = emsS;
        ull et2[13];
#pragma unroll
        for (int i = 0; i < 13; ++i) {
            float lo = __expf(trans[jc * Ln + 2 * i]);
            float hi = (2 * i + 1 < Ln) ? __expf(trans[jc * Ln + 2 * i + 1]) : 0.f;
            et2[i] = pack2(lo, hi);
        }
        float p = (j == colj) ? 1.f : 0.f;
        float C = 0.f;
        float emc = ems[173 * Ln + jc] * lane_okf;   // row 341
        int   mcur = smaskS[341];
        int t = 341;
        for (int g = 0; g < 10; ++g) {
#pragma unroll
            for (int u = 0; u < 16; ++u) { BSTEP(ems, t - 168, t) --t; }
            CRF_RENORM
        }
#pragma unroll
        for (int u = 0; u < 11; ++u) { BSTEP(ems, t - 168, t) --t; }
        CRF_RENORM
        if (lane_ok) g_M[b][colj][j] = p;
        if (j == 0)  g_MC[b][colj] = C;
    }

    // ---- per-batch completion counter; last of 6 combines ----
    __threadfence();
    __syncthreads();
    if (tid == 0) {
        int old = atomicAdd(&g_done[b], 1);
        sflag = (old == 5);
    }
    __syncthreads();

    if (sflag && wid == 0) {
        float d = 0.f;
        if (lane_ok) {
            const float* mrow = &g_M[b][j][0];
#pragma unroll
            for (int k = 0; k < Ln; ++k)
                d += __ldcv(&g_P[b][k]) * __ldcv(mrow + k);
        }
        float Cj = lane_ok ? __ldcv(&g_MC[b][j]) : -1e30f;
        float Cmax = Cj;
#pragma unroll
        for (int off = 16; off; off >>= 1)
            Cmax = fmaxf(Cmax, __shfl_xor_sync(0xffffffffu, Cmax, off));
        float term = lane_ok ? d * __ldcv(&g_Wv[b][j]) * __expf(Cj - Cmax) : 0.f;
#pragma unroll
        for (int off = 16; off; off >>= 1)
            term += __shfl_xor_sync(0xffffffffu, term, off);
        if (j == 0) {
            float denom = __ldcv(&g_Cpw[b][0]) + __ldcv(&g_Cpw[b][1]) + Cmax + __logf(term);
            g_llh[b] = __ldcv(&g_num[b]) - denom;
            __threadfence();
            int old = atomicAdd(&g_cnt, 1);
            if (old == Bn - 1) {
                __threadfence();
                float s = 0.f;
#pragma unroll 8
                for (int i = 0; i < Bn; ++i) s += __ldcv(&g_llh[i]);
                out[0] = -s * (1.0f / 64.0f);
            }
        }
    }
}

// ---------------------------------------------------------------------------
extern "C" void kernel_launch(void* const* d_in, const int* in_sizes, int n_in,
                              void* d_out, int out_size) {
    const float* X      = (const float*)d_in[0];
    const int*   mask   = (const int*)  d_in[1];
    const int*   labels = (const int*)  d_in[2];
    const float* W      = (const float*)d_in[3];
    const float* bias   = (const float*)d_in[4];
    const float* trans  = (const float*)d_in[5];
    const float* st     = (const float*)d_in[6];
    const float* en     = (const float*)d_in[7];
    float* out = (float*)d_out;

    gemm_kernel<<<512, 128, GSMEM>>>(X, W, bias, labels);
    crf_kernel<<<Bn * 6, 160>>>(mask, labels, trans, st, en, out);
}

// round 16
// speedup vs baseline: 1.1640x; 1.0180x over previous
#include <cuda_runtime.h>
#include <math.h>
#include <stdint.h>

#define Bn 64
#define Tn 512
#define Hn 768
#define Ln 25

__device__ __align__(16) float g_eem  [Bn * Tn * Ln];
__device__ __align__(16) float g_emtag[Bn * Tn];
__device__ __align__(16) float g_P [Bn][32];      // fwd result
__device__ __align__(16) float g_Wv[Bn][32];      // bwd result
__device__ __align__(16) float g_M [Bn][25][28];  // middle columns
__device__ float g_MC [Bn][32];                   // column C's
__device__ float g_Cpw[Bn][2];                    // fwd/bwd C
__device__ float g_num[Bn];
__device__ float g_llh[Bn];
__device__ int   g_done[Bn];
__device__ int   g_cnt;

typedef unsigned long long ull;

__device__ __forceinline__ ull fma2(ull a, ull b, ull c) {
    ull d; asm("fma.rn.f32x2 %0, %1, %2, %3;" : "=l"(d) : "l"(a), "l"(b), "l"(c)); return d;
}
__device__ __forceinline__ ull mul2(ull a, ull b) {
    ull d; asm("mul.rn.f32x2 %0, %1, %2;" : "=l"(d) : "l"(a), "l"(b)); return d;
}
__device__ __forceinline__ ull add2(ull a, ull b) {
    ull d; asm("add.rn.f32x2 %0, %1, %2;" : "=l"(d) : "l"(a), "l"(b)); return d;
}
__device__ __forceinline__ float lo2(ull a) {
    unsigned l, h; asm("mov.b64 {%0, %1}, %2;" : "=r"(l), "=r"(h) : "l"(a)); return __uint_as_float(l);
}
__device__ __forceinline__ float hi2(ull a) {
    unsigned l, h; asm("mov.b64 {%0, %1}, %2;" : "=r"(l), "=r"(h) : "l"(a)); return __uint_as_float(h);
}
__device__ __forceinline__ ull pack2(float l, float h) {
    ull d; asm("mov.b64 %0, {%1, %2};" : "=l"(d) : "r"(__float_as_uint(l)), "r"(__float_as_uint(h))); return d;
}
__device__ __forceinline__ uint32_t smem_u32(const void* p) {
    uint32_t a; asm("{ .reg .u64 t; cvta.to.shared.u64 t, %1; cvt.u32.u64 %0, t; }" : "=r"(a) : "l"(p));
    return a;
}
__device__ __forceinline__ void cp16(uint32_t dst, const void* src) {
    asm volatile("cp.async.cg.shared.global [%0], [%1], 16;" :: "r"(dst), "l"(src) : "memory");
}
__device__ __forceinline__ void cp4(uint32_t dst, const void* src) {
    asm volatile("cp.async.ca.shared.global [%0], [%1], 4;" :: "r"(dst), "l"(src) : "memory");
}
#define CP_COMMIT() asm volatile("cp.async.commit_group;" ::: "memory")

#define MMA(D, A0, A1, A2, A3, B0, B1)                                          \
    asm volatile(                                                               \
        "mma.sync.aligned.m16n8k8.row.col.f32.tf32.tf32.f32 "                   \
        "{%0,%1,%2,%3}, {%4,%5,%6,%7}, {%8,%9}, {%0,%1,%2,%3};"                 \
        : "+f"((D)[0]), "+f"((D)[1]), "+f"((D)[2]), "+f"((D)[3])                \
        : "r"(A0), "r"(A1), "r"(A2), "r"(A3), "r"(B0), "r"(B1));

// ---------------------------------------------------------------------------
// Kernel 1: GEMM via mma.sync tf32 — 512 blocks x 64 rows (round-13, proven).
// ---------------------------------------------------------------------------
#define SA0   0
#define SA1   9216
#define SW0   18432
#define SW1   23552
#define SBIAS 28672
#define GSMEM 28800

__global__ __launch_bounds__(128) void gemm_kernel(const float* __restrict__ X,
                                                   const float* __restrict__ W,
                                                   const float* __restrict__ bias,
                                                   const int*   __restrict__ labels) {
    extern __shared__ char smem[];
    const uint32_t sb = smem_u32(smem);
    const int tid  = threadIdx.x;
    const int wid  = tid >> 5;
    const int lid  = tid & 31;
    const int grp  = lid >> 2;
    const int qd   = lid & 3;
    const int row0 = blockIdx.x * 64;

    if (tid == 0 && blockIdx.x < Bn) g_done[blockIdx.x] = 0;
    if (tid == 0 && blockIdx.x == Bn) g_cnt = 0;

    float* bias_s = (float*)(smem + SBIAS);
    if (tid < 32) bias_s[tid] = (tid < Ln) ? bias[tid] : 0.f;

    float c_[4][4];
#pragma unroll
    for (int nt = 0; nt < 4; ++nt)
#pragma unroll
        for (int r = 0; r < 4; ++r) c_[nt][r] = 0.f;

#define STAGE(CK, BUF)                                                          \
    {                                                                           \
        uint32_t ab = sb + ((BUF) ? SA1 : SA0);                                 \
        uint32_t wb = sb + ((BUF) ? SW1 : SW0);                                 \
        _Pragma("unroll")                                                       \
        for (int t = 0; t < 4; ++t) {                                           \
            int i = t * 128 + tid;                                              \
            int r = i >> 3, q = i & 7;                                          \
            cp16(ab + (r * 36 + q * 4) * 4,                                     \
                 X + (size_t)(row0 + r) * Hn + (CK) * 32 + q * 4);              \
        }                                                                       \
        _Pragma("unroll")                                                       \
        for (int t = 0; t < 7; ++t) {                                           \
            int i = t * 128 + tid;                                              \
            if (i < 800) {                                                      \
                int k = i / 25, n = i - k * 25;                                 \
                cp4(wb + (k * 40 + n) * 4, W + (CK) * 800 + i);                 \
            }                                                                   \
        }                                                                       \
        CP_COMMIT();                                                            \
    }

    STAGE(0, 0)
    STAGE(1, 1)

    for (int ck = 0; ck < 24; ++ck) {
        if (ck < 23) asm volatile("cp.async.wait_group 1;" ::: "memory");
        else         asm volatile("cp.async.wait_group 0;" ::: "memory");
        __syncthreads();

        const int buf = ck & 1;
        const float* As = (const float*)(smem + (buf ? SA1 : SA0));
        const float* Ws = (const float*)(smem + (buf ? SW1 : SW0));

#pragma unroll
        for (int ks = 0; ks < 4; ++ks) {
            const int k0 = ks * 8;
            uint32_t a0, a1, a2, a3, b[4][2];
            int r = wid * 16 + grp;
            a0 = __float_as_uint(As[r * 36 + k0 + qd]);
            a1 = __float_as_uint(As[(r + 8) * 36 + k0 + qd]);
            a2 = __float_as_uint(As[r * 36 + k0 + qd + 4]);
            a3 = __float_as_uint(As[(r + 8) * 36 + k0 + qd + 4]);
#pragma unroll
            for (int nt = 0; nt < 4; ++nt) {
                int n = nt * 8 + grp;
                float b0 = (n < Ln) ? Ws[(k0 + qd) * 40 + n] : 0.f;
                float b1 = (n < Ln) ? Ws[(k0 + qd + 4) * 40 + n] : 0.f;
                b[nt][0] = __float_as_uint(b0);
                b[nt][1] = __float_as_uint(b1);
            }
#pragma unroll
            for (int nt = 0; nt < 4; ++nt)
                MMA(c_[nt], a0, a1, a2, a3, b[nt][0], b[nt][1])
        }
        __syncthreads();
        if (ck + 2 < 24) STAGE(ck + 2, buf)
    }

    float* pem = (float*)(smem + 0);
    float* pee = (float*)(smem + 6400);
    {
        int rb = wid * 16 + grp;
#pragma unroll
        for (int nt = 0; nt < 4; ++nt) {
            int col = nt * 8 + 2 * qd;
            if (col < Ln) {
                float v0 = c_[nt][0] + bias_s[col];
                float v2 = c_[nt][2] + bias_s[col];
                pem[rb * Ln + col]       = v0;
                pem[(rb + 8) * Ln + col] = v2;
                pee[rb * Ln + col]       = __expf(v0);
                pee[(rb + 8) * Ln + col] = __expf(v2);
            }
            if (col + 1 < Ln) {
                float v1 = c_[nt][1] + bias_s[col + 1];
                float v3 = c_[nt][3] + bias_s[col + 1];
                pem[rb * Ln + col + 1]       = v1;
                pem[(rb + 8) * Ln + col + 1] = v3;
                pee[rb * Ln + col + 1]       = __expf(v1);
                pee[(rb + 8) * Ln + col + 1] = __expf(v3);
            }
        }
    }
    __syncthreads();
    {
        if (tid < 64) {
            int lab = labels[row0 + tid];
            g_emtag[row0 + tid] = pem[tid * Ln + lab];
        }
        const float4* s1 = (const float4*)pee;
        float4* g1 = (float4*)(g_eem + (size_t)row0 * Ln);
#pragma unroll
        for (int t = 0; t < 4; ++t) {
            int i = t * 128 + tid;
            if (i < 400) g1[i] = s1[i];
        }
    }
}

// ---------------------------------------------------------------------------
// Kernel 2: 3-segment CRF, DISTRIBUTED. Grid 64*6:
//   r==0  : fwd (t=1..170), bwd (t=511..342), numerator  (3 warps)
//   r=1..5: 5 column chains each, m_j = G171..G341 e_j   (5 warps)
// Last of 6 finishers per batch combines; global last writes out.
// ---------------------------------------------------------------------------
#define LN2F 0.6931471805599453f

#define LDW13(PB)                                                               \
        ull w0,w1,w2,w3,w4,w5,w6,w7,w8,w9,w10,w11,w12;                          \
        asm volatile("ld.shared.v2.u64 {%0,%1}, [%2];"                          \
                     : "=l"(w0), "=l"(w1) : "r"(PB));                           \
        asm volatile("ld.shared.v2.u64 {%0,%1}, [%2];"                          \
                     : "=l"(w2), "=l"(w3) : "r"((PB) + 16));                    \
        asm volatile("ld.shared.v2.u64 {%0,%1}, [%2];"                          \
                     : "=l"(w4), "=l"(w5) : "r"((PB) + 32));                    \
        asm volatile("ld.shared.v2.u64 {%0,%1}, [%2];"                          \
                     : "=l"(w6), "=l"(w7) : "r"((PB) + 48));                    \
        asm volatile("ld.shared.v2.u64 {%0,%1}, [%2];"                          \
                     : "=l"(w8), "=l"(w9) : "r"((PB) + 64));                    \
        asm volatile("ld.shared.v2.u64 {%0,%1}, [%2];"                          \
                     : "=l"(w10), "=l"(w11) : "r"((PB) + 80));                  \
        asm volatile("ld.shared.u64 %0, [%1];"                                  \
                     : "=l"(w12) : "r"((PB) + 96));

#define DOT13(ET)                                                               \
        ull A0 = mul2(w0, (ET)[0]);                                             \
        ull A1 = mul2(w1, (ET)[1]);                                             \
        ull A2 = mul2(w2, (ET)[2]);                                             \
        ull A3 = mul2(w3, (ET)[3]);                                             \
        ull A4 = mul2(w4, (ET)[4]);                                             \
        ull A5 = mul2(w5, (ET)[5]);                                             \
        ull A6 = mul2(w6, (ET)[6]);                                             \
        A0 = fma2(w7,  (ET)[7],  A0);                                           \
        A1 = fma2(w8,  (ET)[8],  A1);                                           \
        A2 = fma2(w9,  (ET)[9],  A2);                                           \
        A3 = fma2(w10, (ET)[10], A3);                                           \
        A4 = fma2(w11, (ET)[11], A4);                                           \
        A5 = fma2(w12, (ET)[12], A5);                                           \
        ull T0 = add2(A0, A1);                                                  \
        ull T1 = add2(A2, A3);                                                  \
        ull T2 = add2(A4, A5);                                                  \
        T0 = add2(T0, T1);                                                      \
        T2 = add2(T2, A6);                                                      \
        T0 = add2(T0, T2);

// forward step; TL = local row of current t, TG = absolute t (for mask)
#define FSTEP(EMS, TL, TG)                                                      \
    {                                                                           \
        float emn = (EMS)[((TL) + 1) * Ln + jc];                                \
        int   mn  = smaskS[(TG) + 1];                                           \
        asm volatile("st.shared.b32 [%0], %1;"                                  \
                     :: "r"(pbase + 4u * (unsigned)j),                          \
                        "r"(__float_as_uint(p)) : "memory");                    \
        LDW13(pbase)                                                            \
        DOT13(et2)                                                              \
        float pn = (lo2(T0) + hi2(T0)) * emc;                                   \
        p = mcur ? pn : p;                                                      \
        emc = emn; mcur = mn;                                                   \
    }

// backward step
#define BSTEP(EMS, TL, TG)                                                      \
    {                                                                           \
        float emn = (EMS)[((TL) - 1) * Ln + jc] * lane_okf;                     \
        int   mn  = smaskS[(TG) - 1];                                           \
        float w   = p * emc;                                                    \
        asm volatile("st.shared.b32 [%0], %1;"                                  \
                     :: "r"(pbase + 4u * (unsigned)j),                          \
                        "r"(__float_as_uint(w)) : "memory");                    \
        LDW13(pbase)                                                            \
        DOT13(et2)                                                              \
        float pn = lo2(T0) + hi2(T0);                                           \
        p = mcur ? pn : p;                                                      \
        emc = emn; mcur = mn;                                                   \
    }

#define CRF_RENORM                                                              \
    {                                                                           \
        unsigned mx = __reduce_max_sync(0xffffffffu, __float_as_uint(p));       \
        int e = (int)(mx >> 23);                                                \
        float sc = __uint_as_float((unsigned)(253 - e) << 23);                  \
        p *= sc;                                                                \
        C += (float)(e - 126) * LN2F;                                           \
    }

__global__ __launch_bounds__(160) void crf_kernel(const int* __restrict__ mask,
                                                  const int* __restrict__ labels,
                                                  const float* __restrict__ trans,
                                                  const float* __restrict__ start_t,
                                                  const float* __restrict__ end_t,
                                                  float* __restrict__ out) {
    __shared__ __align__(16) float emsS[8608];   // A: [0..4299]=rows0..171, [4304..]=rows340..511 ; col: rows168..341
    __shared__ __align__(16) float pbufS[5 * 32];
    __shared__ int   smaskS[Tn];
    __shared__ int   sflag;

    const int b   = blockIdx.x / 6;
    const int r   = blockIdx.x % 6;
    const int tid = threadIdx.x;
    const int wid = tid >> 5;
    const int j   = tid & 31;
    const int jc  = (j < Ln) ? j : (Ln - 1);
    const bool lane_ok   = (j < Ln);
    const float lane_okf = lane_ok ? 1.f : 0.f;
    const uint32_t pbase = smem_u32(pbufS) + (unsigned)wid * 128u;

    const float* eemB   = g_eem + (size_t)b * Tn * Ln;
    const float* emtagb = g_emtag + b * Tn;
    const int*   lb     = labels + b * Tn;

    // ---- stage emissions (segment-local) + mask ----
    {
        uint32_t db = smem_u32(emsS);
        if (r == 0) {
            const float4* s0 = (const float4*)eemB;                 // rows 0..171
            const float4* s1 = (const float4*)(eemB + 8500);        // rows 340..511
            for (int i = tid; i < 1075; i += 160) {
                cp16(db + 16u * (unsigned)i, s0 + i);
                cp16(db + 17216u + 16u * (unsigned)i, s1 + i);
            }
        } else {
            const float4* s0 = (const float4*)(eemB + 4200);        // rows 168..341
            for (int i = tid; i < 1088; i += 160)
                cp16(db + 16u * (unsigned)i, s0 + i);
        }
        CP_COMMIT();
    }
    for (int t = tid; t < Tn; t += 160) smaskS[t] = mask[b * Tn + t];
    asm volatile("cp.async.wait_group 0;" ::: "memory");
    __syncthreads();

    if (r == 0) {
        if (wid == 0) {
            // ===== fwd: p = a0^T G1..G170 ===== (local row = t)
            const float* ems = emsS;
            ull et2[13];
#pragma unroll
            for (int i = 0; i < 13; ++i) {
                float lo = __expf(trans[(2 * i) * Ln + jc]);
                float hi = (2 * i + 1 < Ln) ? __expf(trans[(2 * i + 1) * Ln + jc]) : 0.f;
                et2[i] = pack2(lo, hi);
            }
            float p = __expf(start_t[jc]) * ems[jc];
            float C = 0.f;
            float emc = ems[Ln + jc];
            int   mcur = smaskS[1];
            int t = 1;
            for (int g = 0; g < 10; ++g) {
#pragma unroll
                for (int u = 0; u < 16; ++u) { FSTEP(ems, t, t) ++t; }
                CRF_RENORM
            }
#pragma unroll
            for (int u = 0; u < 10; ++u) { FSTEP(ems, t, t) ++t; }
            CRF_RENORM
            g_P[b][j] = lane_ok ? p : 0.f;
            if (j == 0) g_Cpw[b][0] = C;
        } else if (wid == 1) {
            // ===== bwd: w = G342..G511 e ===== (local row = t-340)
            const float* ems = emsS + 4304;
            ull et2[13];
#pragma unroll
            for (int i = 0; i < 13; ++i) {
                float lo = __expf(trans[jc * Ln + 2 * i]);
                float hi = (2 * i + 1 < Ln) ? __expf(trans[jc * Ln + 2 * i + 1]) : 0.f;
                et2[i] = pack2(lo, hi);
            }
            float p = lane_ok ? __expf(end_t[jc]) : 0.f;
            float C = 0.f;
            float emc = ems[171 * Ln + jc] * lane_okf;   // row 511
            int   mcur = smaskS[511];
            int t = 511;
            for (int g = 0; g < 10; ++g) {
#pragma unroll
                for (int u = 0; u < 16; ++u) { BSTEP(ems, t - 340, t) --t; }
                CRF_RENORM
            }
#pragma unroll
            for (int u = 0; u < 10; ++u) { BSTEP(ems, t - 340, t) --t; }
            CRF_RENORM
            g_Wv[b][j] = lane_ok ? p : 0.f;
            if (j == 0) g_Cpw[b][1] = C;
        } else if (wid == 2) {
            // ===== numerator =====
            float numv = 0.f; int msum = 0;
            for (int t = j; t < Tn; t += 32) {
                int m = smaskS[t];
                msum += m;
                if (t == 0)  numv += start_t[lb[0]] + emtagb[0];
                else if (m)  numv += trans[lb[t - 1] * Ln + lb[t]] + emtagb[t];
            }
#pragma unroll
            for (int off = 16; off; off >>= 1) {
                numv += __shfl_xor_sync(0xffffffffu, numv, off);
                msum += __shfl_xor_sync(0xffffffffu, msum, off);
            }
            if (j == 0) g_num[b] = numv + end_t[lb[msum - 1]];
        }
    } else {
        // ===== column m_colj = G171..G341 e_colj ===== (local row = t-168)
        const int colj = (r - 1) * 5 + wid;   // 0..24
        const float* ems = emsS;
        ull et2[13];
#pragma unroll
        for (int i = 0; i < 13; ++i) {
            float lo = __expf(trans[jc * Ln + 2 * i]);
            float hi = (2 * i + 1 < Ln) ? __expf(trans[jc * Ln + 2 * i + 1]) : 0.f;
            et2[i] = pack2(lo, hi);
        }
        float p = (j == colj) ? 1.f : 0.f;
        float C = 0.f;
        float emc = ems[173 * Ln + jc] * lane_okf;   // row 341
        int   mcur = smaskS[341];
        int t = 341;
        for (int g = 0; g < 10; ++g) {
#pragma unroll
            for (int u = 0; u < 16; ++u) { BSTEP(ems, t - 168, t) --t; }
            CRF_RENORM
        }
#pragma unroll
        for (int u = 0; u < 11; ++u) { BSTEP(ems, t - 168, t) --t; }
        CRF_RENORM
        if (lane_ok) g_M[b][colj][j] = p;
        if (j == 0)  g_MC[b][colj] = C;
    }

    // ---- per-batch completion counter; last of 6 combines ----
    __threadfence();
    __syncthreads();
    if (tid == 0) {
        int old = atomicAdd(&g_done[b], 1);
        sflag = (old == 5);
    }
    __syncthreads();

    if (sflag && wid == 0) {
        float d = 0.f;
        if (lane_ok) {
            const float* mrow = &g_M[b][j][0];
#pragma unroll
            for (int k = 0; k < Ln; ++k)
                d += __ldcv(&g_P[b][k]) * __ldcv(mrow + k);
        }
        float Cj = lane_ok ? __ldcv(&g_MC[b][j]) : -1e30f;
        float Cmax = Cj;
#pragma unroll
        for (int off = 16; off; off >>= 1)
            Cmax = fmaxf(Cmax, __shfl_xor_sync(0xffffffffu, Cmax, off));
        float term = lane_ok ? d * __ldcv(&g_Wv[b][j]) * __expf(Cj - Cmax) : 0.f;
#pragma unroll
        for (int off = 16; off; off >>= 1)
            term += __shfl_xor_sync(0xffffffffu, term, off);
        if (j == 0) {
            float denom = __ldcv(&g_Cpw[b][0]) + __ldcv(&g_Cpw[b][1]) + Cmax + __logf(term);
            g_llh[b] = __ldcv(&g_num[b]) - denom;
            __threadfence();
            int old = atomicAdd(&g_cnt, 1);
            if (old == Bn - 1) {
                __threadfence();
                float s = 0.f;
#pragma unroll 8
                for (int i = 0; i < Bn; ++i) s += __ldcv(&g_llh[i]);
                out[0] = -s * (1.0f / 64.0f);
            }
        }
    }
}

// ---------------------------------------------------------------------------
extern "C" void kernel_launch(void* const* d_in, const int* in_sizes, int n_in,
                              void* d_out, int out_size) {
    const float* X      = (const float*)d_in[0];
    const int*   mask   = (const int*)  d_in[1];
    const int*   labels = (const int*)  d_in[2];
    const float* W      = (const float*)d_in[3];
    const float* bias   = (const float*)d_in[4];
    const float* trans  = (const float*)d_in[5];
    const float* st     = (const float*)d_in[6];
    const float* en     = (const float*)d_in[7];
    float* out = (float*)d_out;

    gemm_kernel<<<512, 128, GSMEM>>>(X, W, bias, labels);
    crf_kernel<<<Bn * 6, 160>>>(mask, labels, trans, st, en, out);
}

// round 17
// speedup vs baseline: 1.5000x; 1.2887x over previous
#include <cuda_runtime.h>
#include <math.h>
#include <stdint.h>

#define Bn 64
#define Tn 512
#define Hn 768
#define Ln 25

__device__ __align__(16) float g_eem  [Bn * Tn * Ln];
__device__ __align__(16) float g_emtag[Bn * Tn];
__device__ float g_llh[Bn];
__device__ int   g_done8[Bn];   // gemm blocks finished per batch (self-reset)
__device__ int   g_cnt;         // crf finishers (reset by out-writer)

typedef unsigned long long ull;

__device__ __forceinline__ ull fma2(ull a, ull b, ull c) {
    ull d; asm("fma.rn.f32x2 %0, %1, %2, %3;" : "=l"(d) : "l"(a), "l"(b), "l"(c)); return d;
}
__device__ __forceinline__ ull mul2(ull a, ull b) {
    ull d; asm("mul.rn.f32x2 %0, %1, %2;" : "=l"(d) : "l"(a), "l"(b)); return d;
}
__device__ __forceinline__ ull add2(ull a, ull b) {
    ull d; asm("add.rn.f32x2 %0, %1, %2;" : "=l"(d) : "l"(a), "l"(b)); return d;
}
__device__ __forceinline__ float lo2(ull a) {
    unsigned l, h; asm("mov.b64 {%0, %1}, %2;" : "=r"(l), "=r"(h) : "l"(a)); return __uint_as_float(l);
}
__device__ __forceinline__ float hi2(ull a) {
    unsigned l, h; asm("mov.b64 {%0, %1}, %2;" : "=r"(l), "=r"(h) : "l"(a)); return __uint_as_float(h);
}
__device__ __forceinline__ ull pack2(float l, float h) {
    ull d; asm("mov.b64 %0, {%1, %2};" : "=l"(d) : "r"(__float_as_uint(l)), "r"(__float_as_uint(h))); return d;
}
__device__ __forceinline__ uint32_t smem_u32(const void* p) {
    uint32_t a; asm("{ .reg .u64 t; cvta.to.shared.u64 t, %1; cvt.u32.u64 %0, t; }" : "=r"(a) : "l"(p));
    return a;
}
__device__ __forceinline__ void cp16(uint32_t dst, const void* src) {
    asm volatile("cp.async.cg.shared.global [%0], [%1], 16;" :: "r"(dst), "l"(src) : "memory");
}
__device__ __forceinline__ void cp4(uint32_t dst, const void* src) {
    asm volatile("cp.async.ca.shared.global [%0], [%1], 4;" :: "r"(dst), "l"(src) : "memory");
}
#define CP_COMMIT() asm volatile("cp.async.commit_group;" ::: "memory")

#define MMA(D, A0, A1, A2, A3, B0, B1)                                          \
    asm volatile(                                                               \
        "mma.sync.aligned.m16n8k8.row.col.f32.tf32.tf32.f32 "                   \
        "{%0,%1,%2,%3}, {%4,%5,%6,%7}, {%8,%9}, {%0,%1,%2,%3};"                 \
        : "+f"((D)[0]), "+f"((D)[1]), "+f"((D)[2]), "+f"((D)[3])                \
        : "r"(A0), "r"(A1), "r"(A2), "r"(A3), "r"(B0), "r"(B1));

// smem layout (28.8 KB dynamic), gemm view:
#define SA0   0
#define SA1   9216
#define SW0   18432
#define SW1   23552
#define SBIAS 28672
#define GSMEM 28800
// crf view:
#define CE0   0            // 4 x 1600 floats
#define CPBF  25600        // 2 x 32 floats
#define CMS   25856        // smask 512 ints
#define CCMB  27904        // cmb[64]
#define CSC   28160        // cmbC[2], numsh[2]

#define LN2F 0.6931471805599453f

#define LDW13(PB)                                                               \
        ull w0,w1,w2,w3,w4,w5,w6,w7,w8,w9,w10,w11,w12;                          \
        asm volatile("ld.shared.v2.u64 {%0,%1}, [%2];"                          \
                     : "=l"(w0), "=l"(w1) : "r"(PB));                           \
        asm volatile("ld.shared.v2.u64 {%0,%1}, [%2];"                          \
                     : "=l"(w2), "=l"(w3) : "r"((PB) + 16));                    \
        asm volatile("ld.shared.v2.u64 {%0,%1}, [%2];"                          \
                     : "=l"(w4), "=l"(w5) : "r"((PB) + 32));                    \
        asm volatile("ld.shared.v2.u64 {%0,%1}, [%2];"                          \
                     : "=l"(w6), "=l"(w7) : "r"((PB) + 48));                    \
        asm volatile("ld.shared.v2.u64 {%0,%1}, [%2];"                          \
                     : "=l"(w8), "=l"(w9) : "r"((PB) + 64));                    \
        asm volatile("ld.shared.v2.u64 {%0,%1}, [%2];"                          \
                     : "=l"(w10), "=l"(w11) : "r"((PB) + 80));                  \
        asm volatile("ld.shared.u64 %0, [%1];"                                  \
                     : "=l"(w12) : "r"((PB) + 96));

#define DOT13(ET)                                                               \
        ull A0 = mul2(w0, (ET)[0]);                                             \
        ull A1 = mul2(w1, (ET)[1]);                                             \
        ull A2 = mul2(w2, (ET)[2]);                                             \
        ull A3 = mul2(w3, (ET)[3]);                                             \
        ull A4 = mul2(w4, (ET)[4]);                                             \
        ull A5 = mul2(w5, (ET)[5]);                                             \
        ull A6 = mul2(w6, (ET)[6]);                                             \
        A0 = fma2(w7,  (ET)[7],  A0);                                           \
        A1 = fma2(w8,  (ET)[8],  A1);                                           \
        A2 = fma2(w9,  (ET)[9],  A2);                                           \
        A3 = fma2(w10, (ET)[10], A3);                                           \
        A4 = fma2(w11, (ET)[11], A4);                                           \
        A5 = fma2(w12, (ET)[12], A5);                                           \
        ull T0 = add2(A0, A1);                                                  \
        ull T1 = add2(A2, A3);                                                  \
        ull T2 = add2(A4, A5);                                                  \
        T0 = add2(T0, T1);                                                      \
        T2 = add2(T2, A6);                                                      \
        T0 = add2(T0, T2);

#define CRF_FSTEP(TL, TG)                                                       \
    {                                                                           \
        float emn = ((TL) + 1 < 64) ? emsb[((TL) + 1) * Ln + jc] : 0.f;         \
        asm volatile("st.shared.b32 [%0], %1;"                                  \
                     :: "r"(pbase + 4u * (unsigned)j),                          \
                        "r"(__float_as_uint(p)) : "memory");                    \
        LDW13(pbase)                                                            \
        DOT13(et2)                                                              \
        float pn = (lo2(T0) + hi2(T0)) * emc;                                   \
        unsigned mb = (mwords[(TG) >> 5] >> ((TG) & 31)) & 1u;                  \
        p = mb ? pn : p;                                                        \
        emc = emn;                                                              \
    }

#define CRF_BSTEP(TL, TG)                                                       \
    {                                                                           \
        float emn = ((TL) > 0) ? emsb[((TL) - 1) * Ln + jc] * lane_okf : 0.f;   \
        float w   = p * emc;                                                    \
        asm volatile("st.shared.b32 [%0], %1;"                                  \
                     :: "r"(pbase + 4u * (unsigned)j),                          \
                        "r"(__float_as_uint(w)) : "memory");                    \
        LDW13(pbase)                                                            \
        DOT13(et2)                                                              \
        float pn = lo2(T0) + hi2(T0);                                           \
        unsigned mb = (mwords[(TG) >> 5] >> ((TG) & 31)) & 1u;                  \
        p = mb ? pn : p;                                                        \
        emc = emn;                                                              \
    }

#define CRF_RENORM                                                              \
    {                                                                           \
        unsigned mx = __reduce_max_sync(0xffffffffu, __float_as_uint(p));       \
        int e = (int)(mx >> 23);                                                \
        float sc = __uint_as_float((unsigned)(253 - e) << 23);                  \
        p *= sc;                                                                \
        C += (float)(e - 126) * LN2F;                                           \
    }

#define STAGE_EMS(C, DSTB)                                                      \
    {                                                                           \
        const float* srcp = eemB + (C) * 1600;                                  \
        for (int i = j; i < 400; i += 32)                                       \
            cp16((DSTB) + 16u * (unsigned)i, srcp + 4 * i);                     \
        CP_COMMIT();                                                            \
    }

// ---------------------------------------------------------------------------
// Fused kernel: blocks 0..511 gemm (64 rows each), blocks 512..575 CRF.
// ---------------------------------------------------------------------------
__global__ __launch_bounds__(128) void fused_kernel(
        const float* __restrict__ X,
        const float* __restrict__ W,
        const float* __restrict__ bias,
        const int*   __restrict__ labels,
        const int*   __restrict__ mask,
        const float* __restrict__ trans,
        const float* __restrict__ start_t,
        const float* __restrict__ end_t,
        float* __restrict__ out) {
    extern __shared__ char smem[];
    const uint32_t sb = smem_u32(smem);
    const int tid  = threadIdx.x;
    const int wid  = tid >> 5;
    const int lid  = tid & 31;

    if (blockIdx.x < 512) {
        // ===================== GEMM block =====================
        const int grp  = lid >> 2;
        const int qd   = lid & 3;
        const int row0 = blockIdx.x * 64;

        float* bias_s = (float*)(smem + SBIAS);
        if (tid < 32) bias_s[tid] = (tid < Ln) ? bias[tid] : 0.f;

        float c_[4][4];
#pragma unroll
        for (int nt = 0; nt < 4; ++nt)
#pragma unroll
            for (int r = 0; r < 4; ++r) c_[nt][r] = 0.f;

#define STAGE(CK, BUF)                                                          \
    {                                                                           \
        uint32_t ab = sb + ((BUF) ? SA1 : SA0);                                 \
        uint32_t wb = sb + ((BUF) ? SW1 : SW0);                                 \
        _Pragma("unroll")                                                       \
        for (int t = 0; t < 4; ++t) {                                           \
            int i = t * 128 + tid;                                              \
            int r = i >> 3, q = i & 7;                                          \
            cp16(ab + (r * 36 + q * 4) * 4,                                     \
                 X + (size_t)(row0 + r) * Hn + (CK) * 32 + q * 4);              \
        }                                                                       \
        _Pragma("unroll")                                                       \
        for (int t = 0; t < 7; ++t) {                                           \
            int i = t * 128 + tid;                                              \
            if (i < 800) {                                                      \
                int k = i / 25, n = i - k * 25;                                 \
                cp4(wb + (k * 40 + n) * 4, W + (CK) * 800 + i);                 \
            }                                                                   \
        }                                                                       \
        CP_COMMIT();                                                            \
    }

        STAGE(0, 0)
        STAGE(1, 1)

        for (int ck = 0; ck < 24; ++ck) {
            if (ck < 23) asm volatile("cp.async.wait_group 1;" ::: "memory");
            else         asm volatile("cp.async.wait_group 0;" ::: "memory");
            __syncthreads();

            const int buf = ck & 1;
            const float* As = (const float*)(smem + (buf ? SA1 : SA0));
            const float* Ws = (const float*)(smem + (buf ? SW1 : SW0));

#pragma unroll
            for (int ks = 0; ks < 4; ++ks) {
                const int k0 = ks * 8;
                uint32_t a0, a1, a2, a3, b[4][2];
                int r = wid * 16 + grp;
                a0 = __float_as_uint(As[r * 36 + k0 + qd]);
                a1 = __float_as_uint(As[(r + 8) * 36 + k0 + qd]);
                a2 = __float_as_uint(As[r * 36 + k0 + qd + 4]);
                a3 = __float_as_uint(As[(r + 8) * 36 + k0 + qd + 4]);
#pragma unroll
                for (int nt = 0; nt < 4; ++nt) {
                    int n = nt * 8 + grp;
                    float b0 = (n < Ln) ? Ws[(k0 + qd) * 40 + n] : 0.f;
                    float b1 = (n < Ln) ? Ws[(k0 + qd + 4) * 40 + n] : 0.f;
                    b[nt][0] = __float_as_uint(b0);
                    b[nt][1] = __float_as_uint(b1);
                }
#pragma unroll
                for (int nt = 0; nt < 4; ++nt)
                    MMA(c_[nt], a0, a1, a2, a3, b[nt][0], b[nt][1])
            }
            __syncthreads();
            if (ck + 2 < 24) STAGE(ck + 2, buf)
        }

        float* pem = (float*)(smem + 0);
        float* pee = (float*)(smem + 6400);
        {
            int rb = wid * 16 + grp;
#pragma unroll
            for (int nt = 0; nt < 4; ++nt) {
                int col = nt * 8 + 2 * qd;
                if (col < Ln) {
                    float v0 = c_[nt][0] + bias_s[col];
                    float v2 = c_[nt][2] + bias_s[col];
                    pem[rb * Ln + col]       = v0;
                    pem[(rb + 8) * Ln + col] = v2;
                    pee[rb * Ln + col]       = __expf(v0);
                    pee[(rb + 8) * Ln + col] = __expf(v2);
                }
                if (col + 1 < Ln) {
                    float v1 = c_[nt][1] + bias_s[col + 1];
                    float v3 = c_[nt][3] + bias_s[col + 1];
                    pem[rb * Ln + col + 1]       = v1;
                    pem[(rb + 8) * Ln + col + 1] = v3;
                    pee[rb * Ln + col + 1]       = __expf(v1);
                    pee[(rb + 8) * Ln + col + 1] = __expf(v3);
                }
            }
        }
        __syncthreads();
        {
            if (tid < 64) {
                int lab = labels[row0 + tid];
                g_emtag[row0 + tid] = pem[tid * Ln + lab];
            }
            const float4* s1 = (const float4*)pee;
            float4* g1 = (float4*)(g_eem + (size_t)row0 * Ln);
#pragma unroll
            for (int t = 0; t < 4; ++t) {
                int i = t * 128 + tid;
                if (i < 400) g1[i] = s1[i];
            }
        }
        // release: all writes visible before the per-batch flag increments
        __threadfence();
        __syncthreads();
        if (tid == 0) atomicAdd(&g_done8[blockIdx.x >> 3], 1);
        return;
    }

    // ===================== CRF block (R13 bidirectional) =====================
    const int b  = blockIdx.x - 512;
    const int j  = lid;
    const int jc = (j < Ln) ? j : (Ln - 1);
    const bool  lane_ok  = (j < Ln);
    const float lane_okf = lane_ok ? 1.f : 0.f;

    float* ems0 = (float*)(smem + CE0);
    float* pbufs = (float*)(smem + CPBF);
    int*   smaskp = (int*)(smem + CMS);
    float* cmb   = (float*)(smem + CCMB);
    float* scal  = (float*)(smem + CSC);  // [0]=Cf [1]=Cb [2]=num

    const float* eemB   = g_eem + (size_t)b * Tn * Ln;
    const float* emtagb = g_emtag + b * Tn;
    const int*   lb     = labels + b * Tn;

    // pre-poll: inputs only
    for (int t = tid; t < Tn; t += 128) smaskp[t] = mask[b * Tn + t];
    __syncthreads();

    // wait for this batch's 8 gemm blocks
    if (tid == 0) { while (atomicAdd(&g_done8[b], 0) < 8) {} }
    __syncthreads();
    __threadfence();   // acquire side

    if (wid == 0) {
        // ---- forward: t = 1..255 ----
        const uint32_t pbase = smem_u32(pbufs);
        const uint32_t fb0 = smem_u32(ems0);
        const uint32_t fb1 = smem_u32(ems0 + 1600);
        STAGE_EMS(0, fb0)
        STAGE_EMS(1, fb1)

        unsigned mwords[16];
#pragma unroll
        for (int w = 0; w < 16; ++w)
            mwords[w] = __ballot_sync(0xffffffffu, smaskp[w * 32 + j]);

        ull et2[13];
#pragma unroll
        for (int i = 0; i < 13; ++i) {
            float lo = __expf(trans[(2 * i) * Ln + jc]);
            float hi = (2 * i + 1 < Ln) ? __expf(trans[(2 * i + 1) * Ln + jc]) : 0.f;
            et2[i] = pack2(lo, hi);
        }

        float p = 0.f, C = 0.f;
        for (int c = 0; c < 4; ++c) {
            if (c < 3) asm volatile("cp.async.wait_group 1;" ::: "memory");
            else       asm volatile("cp.async.wait_group 0;" ::: "memory");
            __syncwarp();
            const float* emsb = ems0 + (c & 1) * 1600;
            const int tbase = c * 64;

            if (c == 0) {
                p = __expf(start_t[jc]) * emsb[jc];
                float emc = emsb[Ln + jc];
#pragma unroll
                for (int u = 1; u < 16; ++u) CRF_FSTEP(u, u)
                CRF_RENORM
#pragma unroll
                for (int g = 1; g < 4; ++g) {
#pragma unroll
                    for (int u = 0; u < 16; ++u) CRF_FSTEP(g * 16 + u, g * 16 + u)
                    CRF_RENORM
                }
            } else {
                float emc = emsb[jc];
#pragma unroll
                for (int g = 0; g < 4; ++g) {
#pragma unroll
                    for (int u = 0; u < 16; ++u) CRF_FSTEP(g * 16 + u, tbase + g * 16 + u)
                    CRF_RENORM
                }
            }
            if (c + 2 < 4) STAGE_EMS(c + 2, (c & 1) ? fb1 : fb0)
        }
        cmb[j] = lane_ok ? p : 0.f;
        if (j == 0) scal[0] = C;
    } else if (wid == 1) {
        // ---- backward: t = 511..256 ----
        const uint32_t pbase = smem_u32(pbufs + 32);
        const uint32_t bb0 = smem_u32(ems0 + 3200);
        const uint32_t bb1 = smem_u32(ems0 + 4800);
        STAGE_EMS(7, bb0)
        STAGE_EMS(6, bb1)

        unsigned mwords[16];
#pragma unroll
        for (int w = 0; w < 16; ++w)
            mwords[w] = __ballot_sync(0xffffffffu, smaskp[w * 32 + j]);

        ull et2[13];
#pragma unroll
        for (int i = 0; i < 13; ++i) {
            float lo = __expf(trans[jc * Ln + 2 * i]);
            float hi = (2 * i + 1 < Ln) ? __expf(trans[jc * Ln + 2 * i + 1]) : 0.f;
            et2[i] = pack2(lo, hi);
        }

        float p = lane_ok ? __expf(end_t[jc]) : 0.f;
        float C = 0.f;
        for (int cc = 0; cc < 4; ++cc) {
            if (cc < 3) asm volatile("cp.async.wait_group 1;" ::: "memory");
            else        asm volatile("cp.async.wait_group 0;" ::: "memory");
            __syncwarp();
            const float* emsb = ems0 + 3200 + (cc & 1) * 1600;
            const int tbase = (7 - cc) * 64;

            float emc = emsb[63 * Ln + jc] * lane_okf;
#pragma unroll
            for (int g = 3; g >= 0; --g) {
#pragma unroll
                for (int u = 15; u >= 0; --u) CRF_BSTEP(g * 16 + u, tbase + g * 16 + u)
                CRF_RENORM
            }
            if (cc + 2 < 4) STAGE_EMS(7 - (cc + 2), (cc & 1) ? bb1 : bb0)
        }
        cmb[32 + j] = lane_ok ? p : 0.f;
        if (j == 0) scal[1] = C;
    } else if (wid == 2) {
        // ---- numerator (AFTER poll — reads emtag) ----
        float numv = 0.f; int msum = 0;
        for (int t = j; t < Tn; t += 32) {
            int m = smaskp[t];
            msum += m;
            if (t == 0)  numv += start_t[lb[0]] + emtagb[0];
            else if (m)  numv += trans[lb[t - 1] * Ln + lb[t]] + emtagb[t];
        }
#pragma unroll
        for (int off = 16; off; off >>= 1) {
            numv += __shfl_xor_sync(0xffffffffu, numv, off);
            msum += __shfl_xor_sync(0xffffffffu, msum, off);
        }
        if (j == 0) scal[2] = numv + end_t[lb[msum - 1]];
    }
    __syncthreads();

    if (wid == 0) {
        float z = lane_ok ? cmb[j] * cmb[32 + j] : 0.f;
#pragma unroll
        for (int off = 16; off; off >>= 1) z += __shfl_xor_sync(0xffffffffu, z, off);
        if (j == 0) {
            float denom = scal[0] + scal[1] + __logf(z);
            g_llh[b] = scal[2] - denom;
            __threadfence();
            int old = atomicAdd(&g_cnt, 1);
            if (old == Bn - 1) {
                __threadfence();
                float s = 0.f;
#pragma unroll 8
                for (int i = 0; i < Bn; ++i) s += __ldcv(&g_llh[i]);
                out[0] = -s * (1.0f / 64.0f);
                g_cnt = 0;                    // self-clean for next replay
            }
        }
    }
    __syncthreads();
    if (tid == 0) g_done8[b] = 0;             // self-clean for next replay
}

// ---------------------------------------------------------------------------
extern "C" void kernel_launch(void* const* d_in, const int* in_sizes, int n_in,
                              void* d_out, int out_size) {
    const float* X      = (const float*)d_in[0];
    const int*   mask   = (const int*)  d_in[1];
    const int*   labels = (const int*)  d_in[2];
    const float* W      = (const float*)d_in[3];
    const float* bias   = (const float*)d_in[4];
    const float* trans  = (const float*)d_in[5];
    const float* st     = (const float*)d_in[6];
    const float* en     = (const float*)d_in[7];
    float* out = (float*)d_out;

    fused_kernel<<<576, 128, GSMEM>>>(X, W, bias, labels, mask, trans, st, en, out);
}